// round 7
// baseline (speedup 1.0000x reference)
#include <cuda_runtime.h>
#include <cuda_bf16.h>
#include <math.h>

#define MASK_SIZE 28
#define MASK_CELLS (MASK_SIZE * MASK_SIZE)   // 784
#define MAX_P 1024
#define NTHREADS 512
#define NWARPS (NTHREADS / 32)               // 16
#define CELLS_PER_WARP (MASK_CELLS / NWARPS) // 49

// Scratch (device globals — no allocation allowed)
__device__ float2 g_pp[MAX_P];          // (.x = partial bce sum, .y = pos flag)
__device__ unsigned int g_done = 0;

// ---------------------------------------------------------------------------
// Fused kernel: one block (512 thr / 16 warps) per proposal.
// Warps are AUTONOMOUS: each warp computes the full IoU argmax itself
// (redundant, ALU is idle) then immediately gathers+BCEs its own 49-cell
// slice. No inter-stage barriers; one barrier to collect warp partials.
// Last block finalizes deterministically.
// ---------------------------------------------------------------------------
__global__ void __launch_bounds__(NTHREADS)
fused_maskrcnn_kernel(const float* __restrict__ mask_logits,
                      const float* __restrict__ proposals,
                      const float* __restrict__ gt_boxes,
                      const float* __restrict__ gt_masks,
                      float* __restrict__ out,
                      int P, int G, int H, int W)
{
    int p    = blockIdx.x;
    int tid  = threadIdx.x;
    int lane = tid & 31;
    int wid  = tid >> 5;

    __shared__ float sred[NWARPS];
    __shared__ float sred2[NWARPS];
    __shared__ int   s_is_last;

    // ---- hoisted: logits loads for this warp's 49 cells ----
    const float* lg = mask_logits + (size_t)p * 2 * MASK_CELLS + MASK_CELLS;
    int cell0 = wid * CELLS_PER_WARP + lane;          // lane 0..31
    int cell1 = cell0 + 32;                           // active for lane < 17
    bool act1 = (lane < CELLS_PER_WARP - 32);         // 49-32 = 17
    int  c1   = act1 ? cell1 : cell0;
    float l0 = __ldg(&lg[cell0]);
    float l1 = __ldg(&lg[c1]);

    // ---- per-warp IoU argmax over all G boxes (redundant across warps) ----
    float4 a = __ldg((const float4*)proposals + p);
    float area_a = (a.z - a.x) * (a.w - a.y);

    float best = -1.0f;
    int   bidx = 0x7fffffff;
    for (int g = lane; g < G; g += 32) {
        float4 b = __ldg((const float4*)gt_boxes + g);
        float area_b = (b.z - b.x) * (b.w - b.y);
        float lx = fmaxf(a.x, b.x);
        float ly = fmaxf(a.y, b.y);
        float rx = fminf(a.z, b.z);
        float ry = fminf(a.w, b.w);
        float w = fmaxf(rx - lx, 0.0f);
        float h = fmaxf(ry - ly, 0.0f);
        float inter = w * h;
        float iou = inter / (area_a + area_b - inter);
        if (iou > best) { best = iou; bidx = g; }   // strict >: lowest g kept per lane
    }
    // butterfly argmax: all lanes converge to (max iou, lowest idx on tie)
    #pragma unroll
    for (int off = 16; off > 0; off >>= 1) {
        float ob = __shfl_xor_sync(0xffffffffu, best, off);
        int   oi = __shfl_xor_sync(0xffffffffu, bidx, off);
        if (ob > best || (ob == best && oi < bidx)) { best = ob; bidx = oi; }
    }
    float posw = (best > 0.3f) ? 1.0f : 0.0f;
    int   midx = bidx;

    // softplus term (independent of midx)
    float sp0 = fmaxf(l0, 0.0f) + log1pf(expf(-fabsf(l0)));
    float sp1 = fmaxf(l1, 0.0f) + log1pf(expf(-fabsf(l1)));
    float sp_sum = sp0 + (act1 ? sp1 : 0.0f);

    // ---- gather + l*tgt for this warp's slice (issues immediately) ----
    float acc = 0.0f;
    if (posw != 0.0f) {
        float4 bb = __ldg((const float4*)gt_boxes + midx);
        // truncation toward zero matches astype(int32) for non-negative coords
        int x1 = min(max((int)bb.x, 0), W - 1);
        int y1 = min(max((int)bb.y, 0), H - 1);
        int x2 = max(x1 + 1, min((int)bb.z, W));
        int y2 = max(y1 + 1, min((int)bb.w, H));
        float cw = (float)(x2 - x1);
        float ch = (float)(y2 - y1);
        int cwi = x2 - x1;
        int chi = y2 - y1;

        const float* m = gt_masks + (size_t)midx * H * W;

        float t00[2], t01[2], t10[2], t11[2], wyv[2], wxv[2];
        int cells[2] = {cell0, c1};
        #pragma unroll
        for (int it = 0; it < 2; ++it) {
            int c  = cells[it];
            int yj = c / MASK_SIZE;
            int xi = c - yj * MASK_SIZE;

            float sy = (yj + 0.5f) * ch * (1.0f / MASK_SIZE) - 0.5f;
            sy = fminf(fmaxf(sy, 0.0f), ch - 1.0f);
            float sx = (xi + 0.5f) * cw * (1.0f / MASK_SIZE) - 0.5f;
            sx = fminf(fmaxf(sx, 0.0f), cw - 1.0f);

            int y0 = (int)floorf(sy);
            int x0 = (int)floorf(sx);
            int yp = min(y0 + 1, chi - 1);
            int xp = min(x0 + 1, cwi - 1);
            wyv[it] = sy - (float)y0;
            wxv[it] = sx - (float)x0;

            int Y0 = y1 + y0, Y1 = y1 + yp;
            int X0 = x1 + x0, X1 = x1 + xp;

            t00[it] = __ldg(&m[(size_t)Y0 * W + X0]);
            t01[it] = __ldg(&m[(size_t)Y0 * W + X1]);
            t10[it] = __ldg(&m[(size_t)Y1 * W + X0]);
            t11[it] = __ldg(&m[(size_t)Y1 * W + X1]);
        }
        float lt_sum = 0.0f;
        float lv[2] = {l0, l1};
        #pragma unroll
        for (int it = 0; it < 2; ++it) {
            if (it == 0 || act1) {
                float wy = wyv[it], wx = wxv[it];
                float tgt = (1.0f - wy) * ((1.0f - wx) * t00[it] + wx * t01[it])
                          +          wy * ((1.0f - wx) * t10[it] + wx * t11[it]);
                lt_sum += lv[it] * tgt;
            }
        }
        acc = sp_sum - lt_sum;   // Σ softplus(l) - Σ l*tgt
    }

    // warp sum -> smem
    #pragma unroll
    for (int off = 16; off > 0; off >>= 1)
        acc += __shfl_down_sync(0xffffffffu, acc, off);
    if (lane == 0) sred[wid] = acc;
    __syncthreads();
    if (tid == 0) {
        float s = 0.0f;
        #pragma unroll
        for (int i = 0; i < NWARPS; ++i) s += sred[i];
        g_pp[p] = make_float2(s, posw);
        __threadfence();
        unsigned int prev = atomicAdd(&g_done, 1u);
        s_is_last = (prev == (unsigned int)(gridDim.x - 1)) ? 1 : 0;
    }
    __syncthreads();

    // ---- last block finalizes ----
    if (s_is_last) {
        float s = 0.0f, c = 0.0f;
        for (int i = tid; i < P; i += NTHREADS) {
            float2 v = g_pp[i];
            s += v.x;
            c += v.y;
        }
        #pragma unroll
        for (int off = 16; off > 0; off >>= 1) {
            s += __shfl_down_sync(0xffffffffu, s, off);
            c += __shfl_down_sync(0xffffffffu, c, off);
        }
        if (lane == 0) { sred[wid] = s; sred2[wid] = c; }
        __syncthreads();
        if (tid == 0) {
            float ts = 0.0f, tc = 0.0f;
            #pragma unroll
            for (int i = 0; i < NWARPS; ++i) { ts += sred[i]; tc += sred2[i]; }
            float denom = fmaxf(tc, 1.0f) * (float)MASK_CELLS;
            out[0] = (tc > 0.0f) ? (ts / denom) : 0.0f;
            g_done = 0;   // reset for next graph replay
        }
    }
}

// ---------------------------------------------------------------------------
// Inputs (metadata order):
//  0: mask_logits  float32  P*2*28*28
//  1: proposals    float32  P*4
//  2: gt_boxes     float32  G*4
//  3: gt_masks     float32  G*H*W
//  4: gt_labels    int32    G        (unused by the reference math)
// Output: scalar float32
// ---------------------------------------------------------------------------
extern "C" void kernel_launch(void* const* d_in, const int* in_sizes, int n_in,
                              void* d_out, int out_size)
{
    const float* mask_logits = (const float*)d_in[0];
    const float* proposals   = (const float*)d_in[1];
    const float* gt_boxes    = (const float*)d_in[2];
    const float* gt_masks    = (const float*)d_in[3];

    int P = in_sizes[1] / 4;
    int G = in_sizes[2] / 4;
    int HW = in_sizes[3] / G;
    int H = 520;
    int W = HW / H;

    float* out = (float*)d_out;

    fused_maskrcnn_kernel<<<P, NTHREADS>>>(mask_logits, proposals, gt_boxes,
                                           gt_masks, out, P, G, H, W);
}

// round 8
// speedup vs baseline: 1.5655x; 1.5655x over previous
#include <cuda_runtime.h>
#include <cuda_bf16.h>
#include <math.h>

#define MASK_SIZE 28
#define MASK_CELLS (MASK_SIZE * MASK_SIZE)   // 784
#define MAX_P 1024
#define MAX_G 512
#define NTHREADS 512
#define NWARPS (NTHREADS / 32)               // 16
#define NCELLS 2                              // cells per thread

// Scratch (device globals — no allocation allowed)
__device__ float2 g_pp[MAX_P];          // (.x = partial bce sum, .y = pos flag)
__device__ unsigned int g_done = 0;

// ---------------------------------------------------------------------------
// Fused kernel: one block (512 thr / 16 warps) per proposal.
//  Entry: hoist logits loads (independent of IoU result)
//  A: IoU row p over G gt boxes; boxes staged to smem; warp partial argmax
//     -> smem; ONE barrier; every warp redundantly reduces 16 partials.
//  B: winning box read from smem; bilinear gather (front-batched) + BCE.
//  C: last block finalizes deterministically.
// ---------------------------------------------------------------------------
__global__ void __launch_bounds__(NTHREADS)
fused_maskrcnn_kernel(const float* __restrict__ mask_logits,
                      const float* __restrict__ proposals,
                      const float* __restrict__ gt_boxes,
                      const float* __restrict__ gt_masks,
                      float* __restrict__ out,
                      int P, int G, int H, int W)
{
    int p    = blockIdx.x;
    int tid  = threadIdx.x;
    int lane = tid & 31;
    int wid  = tid >> 5;

    __shared__ float4 sbox[MAX_G];
    __shared__ float  swb[NWARPS];
    __shared__ int    swi[NWARPS];
    __shared__ float  sred[NWARPS];
    __shared__ float  sred2[NWARPS];
    __shared__ int    s_is_last;

    // ---- hoisted: logits loads (independent of IoU result) ----
    const float* lg = mask_logits + (size_t)p * 2 * MASK_CELLS + MASK_CELLS;
    float lgt[NCELLS];
    bool  act[NCELLS];
    int   cellv[NCELLS];
    #pragma unroll
    for (int it = 0; it < NCELLS; ++it) {
        int cell = tid + it * NTHREADS;
        act[it]  = (cell < MASK_CELLS);
        cellv[it] = act[it] ? cell : 0;
        lgt[it]  = __ldg(&lg[cellv[it]]);
    }

    // ---------------- Stage A: IoU row + argmax ----------------
    float4 a = __ldg((const float4*)proposals + p);
    float area_a = (a.z - a.x) * (a.w - a.y);

    float best = -1.0f;
    int   bidx = 0x7fffffff;
    for (int g = tid; g < G; g += NTHREADS) {
        float4 b = __ldg((const float4*)gt_boxes + g);
        sbox[g] = b;                                  // stage for later smem read
        float area_b = (b.z - b.x) * (b.w - b.y);
        float lx = fmaxf(a.x, b.x);
        float ly = fmaxf(a.y, b.y);
        float rx = fminf(a.z, b.z);
        float ry = fminf(a.w, b.w);
        float w = fmaxf(rx - lx, 0.0f);
        float h = fmaxf(ry - ly, 0.0f);
        float inter = w * h;
        float iou = inter / (area_a + area_b - inter);
        if (iou > best) { best = iou; bidx = g; }   // strict >: lowest g kept
    }
    #pragma unroll
    for (int off = 16; off > 0; off >>= 1) {
        float ob = __shfl_down_sync(0xffffffffu, best, off);
        int   oi = __shfl_down_sync(0xffffffffu, bidx, off);
        if (ob > best || (ob == best && oi < bidx)) { best = ob; bidx = oi; }
    }
    if (lane == 0) { swb[wid] = best; swi[wid] = bidx; }

    // softplus term while the barrier drains (independent of midx)
    float sp_sum = 0.0f;
    #pragma unroll
    for (int it = 0; it < NCELLS; ++it) {
        float l = lgt[it];
        float sp = fmaxf(l, 0.0f) + log1pf(expf(-fabsf(l)));   // == logaddexp(l,0)
        if (act[it]) sp_sum += sp;
    }

    __syncthreads();   // single barrier: smem partials + sbox visible

    // every warp reduces the 16 partials itself (cheap; no 2nd barrier)
    float b2 = (lane < NWARPS) ? swb[lane] : -1.0f;
    int   i2 = (lane < NWARPS) ? swi[lane] : 0x7fffffff;
    #pragma unroll
    for (int off = 8; off > 0; off >>= 1) {
        float ob = __shfl_xor_sync(0xffffffffu, b2, off);
        int   oi = __shfl_xor_sync(0xffffffffu, i2, off);
        if (ob > b2 || (ob == b2 && oi < i2)) { b2 = ob; i2 = oi; }
    }
    // lanes 16..31 hold junk-reduced values; broadcast lane 0's result
    float maxiou = __shfl_sync(0xffffffffu, b2, 0);
    int   midx   = __shfl_sync(0xffffffffu, i2, 0);
    float posw   = (maxiou > 0.3f) ? 1.0f : 0.0f;

    // ---------------- Stage B: target gather + l*tgt ----------------
    float acc = 0.0f;
    if (posw != 0.0f) {
        float4 bb = sbox[midx];                       // smem: ~29 cyc, not DRAM
        // truncation toward zero matches astype(int32) for non-negative coords
        int x1 = min(max((int)bb.x, 0), W - 1);
        int y1 = min(max((int)bb.y, 0), H - 1);
        int x2 = max(x1 + 1, min((int)bb.z, W));
        int y2 = max(y1 + 1, min((int)bb.w, H));
        float cw = (float)(x2 - x1);
        float ch = (float)(y2 - y1);
        int cwi = x2 - x1;
        int chi = y2 - y1;

        const float* m = gt_masks + (size_t)midx * H * W;

        float t00[NCELLS], t01[NCELLS], t10[NCELLS], t11[NCELLS];
        float wyv[NCELLS], wxv[NCELLS];
        #pragma unroll
        for (int it = 0; it < NCELLS; ++it) {
            int c  = cellv[it];
            int yj = c / MASK_SIZE;
            int xi = c - yj * MASK_SIZE;

            float sy = (yj + 0.5f) * ch * (1.0f / MASK_SIZE) - 0.5f;
            sy = fminf(fmaxf(sy, 0.0f), ch - 1.0f);
            float sx = (xi + 0.5f) * cw * (1.0f / MASK_SIZE) - 0.5f;
            sx = fminf(fmaxf(sx, 0.0f), cw - 1.0f);

            int y0 = (int)floorf(sy);
            int x0 = (int)floorf(sx);
            int yp = min(y0 + 1, chi - 1);
            int xp = min(x0 + 1, cwi - 1);
            wyv[it] = sy - (float)y0;
            wxv[it] = sx - (float)x0;

            int Y0 = y1 + y0, Y1 = y1 + yp;
            int X0 = x1 + x0, X1 = x1 + xp;

            t00[it] = __ldg(&m[(size_t)Y0 * W + X0]);
            t01[it] = __ldg(&m[(size_t)Y0 * W + X1]);
            t10[it] = __ldg(&m[(size_t)Y1 * W + X0]);
            t11[it] = __ldg(&m[(size_t)Y1 * W + X1]);
        }
        float lt_sum = 0.0f;
        #pragma unroll
        for (int it = 0; it < NCELLS; ++it) {
            if (act[it]) {
                float wy = wyv[it], wx = wxv[it];
                float tgt = (1.0f - wy) * ((1.0f - wx) * t00[it] + wx * t01[it])
                          +          wy * ((1.0f - wx) * t10[it] + wx * t11[it]);
                lt_sum += lgt[it] * tgt;
            }
        }
        acc = sp_sum - lt_sum;   // Σ softplus(l) - Σ l*tgt  (exact regroup of ref sum)
    }

    // block sum: warp shuffle, then cross-warp
    #pragma unroll
    for (int off = 16; off > 0; off >>= 1)
        acc += __shfl_down_sync(0xffffffffu, acc, off);
    if (lane == 0) sred[wid] = acc;
    __syncthreads();
    if (tid == 0) {
        float s = 0.0f;
        #pragma unroll
        for (int i = 0; i < NWARPS; ++i) s += sred[i];
        g_pp[p] = make_float2(s, posw);
        __threadfence();
        unsigned int prev = atomicAdd(&g_done, 1u);
        s_is_last = (prev == (unsigned int)(gridDim.x - 1)) ? 1 : 0;
    }
    __syncthreads();

    // ---------------- Stage C: last block finalizes ----------------
    if (s_is_last) {
        float s = 0.0f, c = 0.0f;
        for (int i = tid; i < P; i += NTHREADS) {
            float2 v = g_pp[i];
            s += v.x;
            c += v.y;
        }
        #pragma unroll
        for (int off = 16; off > 0; off >>= 1) {
            s += __shfl_down_sync(0xffffffffu, s, off);
            c += __shfl_down_sync(0xffffffffu, c, off);
        }
        if (lane == 0) { sred[wid] = s; sred2[wid] = c; }
        __syncthreads();
        if (tid == 0) {
            float ts = 0.0f, tc = 0.0f;
            #pragma unroll
            for (int i = 0; i < NWARPS; ++i) { ts += sred[i]; tc += sred2[i]; }
            float denom = fmaxf(tc, 1.0f) * (float)MASK_CELLS;
            out[0] = (tc > 0.0f) ? (ts / denom) : 0.0f;
            g_done = 0;   // reset for next graph replay
        }
    }
}

// ---------------------------------------------------------------------------
// Inputs (metadata order):
//  0: mask_logits  float32  P*2*28*28
//  1: proposals    float32  P*4
//  2: gt_boxes     float32  G*4
//  3: gt_masks     float32  G*H*W
//  4: gt_labels    int32    G        (unused by the reference math)
// Output: scalar float32
// ---------------------------------------------------------------------------
extern "C" void kernel_launch(void* const* d_in, const int* in_sizes, int n_in,
                              void* d_out, int out_size)
{
    const float* mask_logits = (const float*)d_in[0];
    const float* proposals   = (const float*)d_in[1];
    const float* gt_boxes    = (const float*)d_in[2];
    const float* gt_masks    = (const float*)d_in[3];

    int P = in_sizes[1] / 4;
    int G = in_sizes[2] / 4;
    int HW = in_sizes[3] / G;
    int H = 520;
    int W = HW / H;

    float* out = (float*)d_out;

    fused_maskrcnn_kernel<<<P, NTHREADS>>>(mask_logits, proposals, gt_boxes,
                                           gt_masks, out, P, G, H, W);
}